// round 2
// baseline (speedup 1.0000x reference)
#include <cuda_runtime.h>
#include <cuda_bf16.h>
#include <math.h>

// Problem constants
#define Bb   4
#define Cc   64
#define Hh   96
#define Ww   96
#define HW   (Hh*Ww)            // 9216
#define Oo   64
#define CIN3 (3*Cc)             // 192
#define IMG  (Cc*HW)            // 589824
#define NPIX (Bb*HW)            // 36864
#define NCHUNK 24               // 192 / 8 channels per chunk

// Scratch (no cudaMalloc allowed)
__device__ float g_offset[Bb * 18 * HW];       // [4][18][96][96]
__device__ float g_x[Bb * HW * CIN3];          // NHWC packed (ref|dist|diff)
__device__ float g_w2[NCHUNK * 9 * 8 * Oo];    // [chunk][k][cl][o]

// ---------------- f32x2 packed-FMA helpers (sm_103a) ----------------
__device__ __forceinline__ void ffma2(unsigned long long& c,
                                      unsigned long long a,
                                      unsigned long long b) {
    asm("fma.rn.f32x2 %0, %1, %2, %0;" : "+l"(c) : "l"(a), "l"(b));
}
__device__ __forceinline__ unsigned long long dup2(float x) {
    unsigned long long d;
    asm("mov.b64 %0, {%1, %1};" : "=l"(d) : "r"(__float_as_uint(x)));
    return d;
}
__device__ __forceinline__ void unpk2(float& lo, float& hi, unsigned long long v) {
    unsigned int l, h;
    asm("mov.b64 {%0, %1}, %2;" : "=r"(l), "=r"(h) : "l"(v));
    lo = __uint_as_float(l); hi = __uint_as_float(h);
}

// ---------------------------------------------------------------------------
// Kernel 1: diff + NHWC repack.  g_x[b][pix][c], c: 0-63 ref, 64-127 dist,
// 128-191 diff.  Also writes diff (NCHW) to the second output tensor.
// 1152 blocks: b(4) x 288 pixel tiles of 32.
// ---------------------------------------------------------------------------
__global__ __launch_bounds__(256) void repack_kernel(
        const float* __restrict__ ref, const float* __restrict__ dist,
        float* __restrict__ out_diff, float* __restrict__ xpk) {
    __shared__ float t[CIN3][33];
    int tid  = threadIdx.x;
    int b    = blockIdx.x / 288;
    int pix0 = (blockIdx.x % 288) * 32;

    for (int i = tid; i < CIN3 * 32; i += 256) {
        int c = i >> 5, p = i & 31;
        int pix = pix0 + p;
        float v;
        if (c < Cc) {
            v = __ldg(ref + b * IMG + c * HW + pix);
        } else if (c < 2 * Cc) {
            v = __ldg(dist + b * IMG + (c - Cc) * HW + pix);
        } else {
            int cc = c - 2 * Cc;
            float r = __ldg(ref  + b * IMG + cc * HW + pix);
            float d = __ldg(dist + b * IMG + cc * HW + pix);
            v = (r - d) * (r - d);
            out_diff[b * IMG + cc * HW + pix] = v;
        }
        t[c][p] = v;
    }
    __syncthreads();
    for (int i = tid; i < 32 * 48; i += 256) {
        int p = i / 48, c4 = i % 48;
        int c = c4 * 4;
        float4 v = make_float4(t[c][p], t[c + 1][p], t[c + 2][p], t[c + 3][p]);
        ((float4*)(xpk + (size_t)(b * HW + pix0 + p) * CIN3))[c4] = v;
    }
}

// ---------------------------------------------------------------------------
// Kernel 2: offset conv3x3 (Cin=64 -> 18), unchanged from round 1
// ---------------------------------------------------------------------------
__global__ __launch_bounds__(256) void offset_conv_kernel(
        const float* __restrict__ ref,
        const float* __restrict__ ow, const float* __restrict__ ob,
        float* __restrict__ out) {
    __shared__ __align__(16) float s_w[576 * 20];
    int tid = threadIdx.x;
    for (int i = tid; i < 18 * 576; i += 256) {
        int o = i / 576, ck = i % 576;
        s_w[ck * 20 + o] = ow[i];
    }
    __syncthreads();

    int p = blockIdx.x * 256 + tid;
    int b = p / HW;
    int pix = p % HW;
    int y = pix / Ww, x = pix % Ww;

    int  idx9[9]; bool ok9[9];
#pragma unroll
    for (int ky = 0; ky < 3; ky++)
#pragma unroll
        for (int kx = 0; kx < 3; kx++) {
            int yy = y + ky - 1, xx = x + kx - 1;
            bool ok = (yy >= 0) && (yy < Hh) && (xx >= 0) && (xx < Ww);
            ok9[ky * 3 + kx] = ok;
            idx9[ky * 3 + kx] = (ok ? yy : 0) * Ww + (ok ? xx : 0);
        }

    float acc[18];
#pragma unroll
    for (int o = 0; o < 18; o++) acc[o] = 0.f;

    const float* xb = ref + b * IMG;
    for (int c = 0; c < Cc; c++) {
        const float* xc = xb + c * HW;
#pragma unroll
        for (int k = 0; k < 9; k++) {
            float v = ok9[k] ? __ldg(xc + idx9[k]) : 0.f;
            int base = (c * 9 + k) * 20;
            float4 w0 = *(const float4*)&s_w[base];
            float4 w1 = *(const float4*)&s_w[base + 4];
            float4 w2 = *(const float4*)&s_w[base + 8];
            float4 w3 = *(const float4*)&s_w[base + 12];
            float  wa = s_w[base + 16];
            float  wb = s_w[base + 17];
            acc[0]  += v * w0.x;  acc[1]  += v * w0.y;  acc[2]  += v * w0.z;  acc[3]  += v * w0.w;
            acc[4]  += v * w1.x;  acc[5]  += v * w1.y;  acc[6]  += v * w1.z;  acc[7]  += v * w1.w;
            acc[8]  += v * w2.x;  acc[9]  += v * w2.y;  acc[10] += v * w2.z;  acc[11] += v * w2.w;
            acc[12] += v * w3.x;  acc[13] += v * w3.y;  acc[14] += v * w3.z;  acc[15] += v * w3.w;
            acc[16] += v * wa;    acc[17] += v * wb;
        }
    }
#pragma unroll
    for (int o = 0; o < 18; o++)
        out[(b * 18 + o) * HW + pix] = acc[o] + __ldg(ob + o);
}

// ---------------------------------------------------------------------------
// Kernel 3: weight rearrange dw[o][c][k] -> g_w2[chunk][k][cl][o], c=chunk*8+cl
// ---------------------------------------------------------------------------
__global__ void wprep_kernel(const float* __restrict__ dw, float* __restrict__ w2) {
    int i = blockIdx.x * blockDim.x + threadIdx.x;
    if (i < NCHUNK * 9 * 8 * Oo) {
        int o  = i & 63;
        int t  = i >> 6;
        int cl = t & 7;
        int t2 = t >> 3;
        int k  = t2 % 9;
        int ch = t2 / 9;
        w2[i] = dw[o * (CIN3 * 9) + (ch * 8 + cl) * 9 + k];
    }
}

// ---------------------------------------------------------------------------
// Kernel 4: deformable conv, implicit GEMM with f32x2 FFMA.
// Block: M=128 px, N=64 out, 128 threads (16 tx * 8 ty), 8x8 microtile.
// Chunk = 8 channels -> 72 k-steps/chunk, 24 chunks.
// dyn smem: As[72][128] | Ws[72][64] | tw float4[1152] | ti int4[1152] = 90KB
// ---------------------------------------------------------------------------
__global__ __launch_bounds__(128) void deform_kernel(
        const float* __restrict__ db, float* __restrict__ out) {
    extern __shared__ float smem[];
    float*  As = smem;                    // 72*128 = 9216 floats
    float*  Ws = smem + 9216;             // 72*64  = 4608 floats
    float4* tw = (float4*)(smem + 13824); // 1152 float4
    int4*   ti = (int4*)(smem + 18432);   // 1152 int4

    int tid  = threadIdx.x;
    int b    = blockIdx.x / 72;
    int pix0 = (blockIdx.x % 72) * 128;

    // ---- bilinear meta: 128 px x 9 kernel positions ----
    for (int i = tid; i < 1152; i += 128) {
        int k = i >> 7, p = i & 127;
        int pix = pix0 + p;
        int y = pix / Ww, x = pix - (pix / Ww) * Ww;
        float offy = g_offset[(b * 18 + 2 * k)     * HW + pix];
        float offx = g_offset[(b * 18 + 2 * k + 1) * HW + pix];
        float py = (float)(y - 1 + k / 3) + offy;
        float px = (float)(x - 1 + k % 3) + offx;
        float fy = floorf(py), fx = floorf(px);
        int y0 = (int)fy, x0 = (int)fx;
        float dy = py - fy, dx = px - fx;
        float wv[4]; int iv[4];
#pragma unroll
        for (int t = 0; t < 4; t++) {
            int yt = y0 + (t >> 1);
            int xt = x0 + (t & 1);
            float wt = ((t >> 1) ? dy : (1.f - dy)) * ((t & 1) ? dx : (1.f - dx));
            bool valid = (yt >= 0) && (yt < Hh) && (xt >= 0) && (xt < Ww);
            int yc = yt < 0 ? 0 : (yt > Hh - 1 ? Hh - 1 : yt);
            int xc = xt < 0 ? 0 : (xt > Ww - 1 ? Ww - 1 : xt);
            wv[t] = valid ? wt : 0.f;
            iv[t] = (yc * Ww + xc) * CIN3;     // premultiplied NHWC row offset
        }
        tw[i] = make_float4(wv[0], wv[1], wv[2], wv[3]);
        ti[i] = make_int4(iv[0], iv[1], iv[2], iv[3]);
    }

    unsigned long long acc[8][4];
#pragma unroll
    for (int i = 0; i < 8; i++)
#pragma unroll
        for (int j = 0; j < 4; j++) acc[i][j] = 0ull;

    int tx = tid & 15;   // 16 groups of 8 px
    int ty = tid >> 4;   // 8 groups of 8 out
    const float* a_base = As + tx * 8;
    const float* w_base = Ws + ty * 8;
    const float* xb = g_x + (size_t)b * HW * CIN3;

    for (int ch = 0; ch < NCHUNK; ch++) {
        __syncthreads();   // previous GEMM done (meta ready on first iter)
        // stage weights (contiguous 4608 floats)
        {
            const float4* wsrc = (const float4*)(g_w2 + ch * 4608);
            float4* wdst = (float4*)Ws;
            for (int i = tid; i < 1152; i += 128) wdst[i] = __ldg(wsrc + i);
        }
        // build sampled A tile: rows s = k*8+cl, 8 channels per (p,k)
        const float* xc = xb + ch * 8;
        for (int i = tid; i < 1152; i += 128) {
            float4 w = tw[i]; int4 id = ti[i];
            const float4* p00 = (const float4*)(xc + id.x);
            const float4* p01 = (const float4*)(xc + id.y);
            const float4* p10 = (const float4*)(xc + id.z);
            const float4* p11 = (const float4*)(xc + id.w);
            float4 a0 = __ldg(p00), a1 = __ldg(p00 + 1);
            float4 b0 = __ldg(p01), b1 = __ldg(p01 + 1);
            float4 c0 = __ldg(p10), c1 = __ldg(p10 + 1);
            float4 d0 = __ldg(p11), d1 = __ldg(p11 + 1);
            float4 vlo, vhi;
            vlo.x = fmaf(w.x, a0.x, fmaf(w.y, b0.x, fmaf(w.z, c0.x, w.w * d0.x)));
            vlo.y = fmaf(w.x, a0.y, fmaf(w.y, b0.y, fmaf(w.z, c0.y, w.w * d0.y)));
            vlo.z = fmaf(w.x, a0.z, fmaf(w.y, b0.z, fmaf(w.z, c0.z, w.w * d0.z)));
            vlo.w = fmaf(w.x, a0.w, fmaf(w.y, b0.w, fmaf(w.z, c0.w, w.w * d0.w)));
            vhi.x = fmaf(w.x, a1.x, fmaf(w.y, b1.x, fmaf(w.z, c1.x, w.w * d1.x)));
            vhi.y = fmaf(w.x, a1.y, fmaf(w.y, b1.y, fmaf(w.z, c1.y, w.w * d1.y)));
            vhi.z = fmaf(w.x, a1.z, fmaf(w.y, b1.z, fmaf(w.z, c1.z, w.w * d1.z)));
            vhi.w = fmaf(w.x, a1.w, fmaf(w.y, b1.w, fmaf(w.z, c1.w, w.w * d1.w)));
            int k = i >> 7, p = i & 127;
            float* dst = As + (k * 8) * 128 + p;
            dst[0]   = vlo.x; dst[128] = vlo.y; dst[256] = vlo.z; dst[384] = vlo.w;
            dst[512] = vhi.x; dst[640] = vhi.y; dst[768] = vhi.z; dst[896] = vhi.w;
        }
        __syncthreads();
        // GEMM: 72 k-steps, 8x8 microtile, packed f32x2 FMA
#pragma unroll 8
        for (int s = 0; s < 72; s++) {
            float4 alo = *(const float4*)(a_base + s * 128);
            float4 ahi = *(const float4*)(a_base + s * 128 + 4);
            ulonglong2 wlo = *(const ulonglong2*)(w_base + s * 64);
            ulonglong2 whi = *(const ulonglong2*)(w_base + s * 64 + 4);
            unsigned long long ad[8];
            ad[0] = dup2(alo.x); ad[1] = dup2(alo.y);
            ad[2] = dup2(alo.z); ad[3] = dup2(alo.w);
            ad[4] = dup2(ahi.x); ad[5] = dup2(ahi.y);
            ad[6] = dup2(ahi.z); ad[7] = dup2(ahi.w);
#pragma unroll
            for (int px = 0; px < 8; px++) {
                ffma2(acc[px][0], ad[px], wlo.x);
                ffma2(acc[px][1], ad[px], wlo.y);
                ffma2(acc[px][2], ad[px], whi.x);
                ffma2(acc[px][3], ad[px], whi.y);
            }
        }
    }

    // ---- epilogue: bias + relu ----
    int pxb = pix0 + tx * 8;
#pragma unroll
    for (int j = 0; j < 4; j++) {
        int o0 = ty * 8 + 2 * j;
        float bias0 = __ldg(db + o0);
        float bias1 = __ldg(db + o0 + 1);
        float lo[8], hi[8];
#pragma unroll
        for (int px = 0; px < 8; px++) unpk2(lo[px], hi[px], acc[px][j]);
        float* r0 = out + (b * Oo + o0) * HW + pxb;
        float* r1 = out + (b * Oo + o0 + 1) * HW + pxb;
        float4 v;
        v = make_float4(fmaxf(lo[0] + bias0, 0.f), fmaxf(lo[1] + bias0, 0.f),
                        fmaxf(lo[2] + bias0, 0.f), fmaxf(lo[3] + bias0, 0.f));
        *(float4*)r0 = v;
        v = make_float4(fmaxf(lo[4] + bias0, 0.f), fmaxf(lo[5] + bias0, 0.f),
                        fmaxf(lo[6] + bias0, 0.f), fmaxf(lo[7] + bias0, 0.f));
        *(float4*)(r0 + 4) = v;
        v = make_float4(fmaxf(hi[0] + bias1, 0.f), fmaxf(hi[1] + bias1, 0.f),
                        fmaxf(hi[2] + bias1, 0.f), fmaxf(hi[3] + bias1, 0.f));
        *(float4*)r1 = v;
        v = make_float4(fmaxf(hi[4] + bias1, 0.f), fmaxf(hi[5] + bias1, 0.f),
                        fmaxf(hi[6] + bias1, 0.f), fmaxf(hi[7] + bias1, 0.f));
        *(float4*)(r1 + 4) = v;
    }
}

// ---------------------------------------------------------------------------
extern "C" void kernel_launch(void* const* d_in, const int* in_sizes, int n_in,
                              void* d_out, int out_size) {
    const float* ref  = (const float*)d_in[0];
    const float* dist = (const float*)d_in[1];
    const float* ow   = (const float*)d_in[2];
    const float* ob   = (const float*)d_in[3];
    const float* dw   = (const float*)d_in[4];
    const float* db   = (const float*)d_in[5];
    float* out = (float*)d_out;
    float* out_feat = out;
    float* out_diff = out + Bb * IMG;

    float* offbuf; cudaGetSymbolAddress((void**)&offbuf, g_offset);
    float* xpk;    cudaGetSymbolAddress((void**)&xpk, g_x);
    float* w2;     cudaGetSymbolAddress((void**)&w2, g_w2);

    const int DSMEM = 23040 * 4;   // 92160 B
    cudaFuncSetAttribute(deform_kernel,
                         cudaFuncAttributeMaxDynamicSharedMemorySize, DSMEM);

    repack_kernel<<<Bb * 288, 256>>>(ref, dist, out_diff, xpk);
    offset_conv_kernel<<<NPIX / 256, 256>>>(ref, ow, ob, offbuf);
    wprep_kernel<<<(NCHUNK * 9 * 8 * Oo + 255) / 256, 256>>>(dw, w2);
    deform_kernel<<<NPIX / 128, 128, DSMEM>>>(db, out_feat);
}

// round 4
// speedup vs baseline: 2.0998x; 2.0998x over previous
#include <cuda_runtime.h>
#include <cuda_bf16.h>
#include <math.h>
#include <stdint.h>

// Problem constants
#define Bb   4
#define Cc   64
#define Hh   96
#define Ww   96
#define HW   (Hh*Ww)            // 9216
#define Oo   64
#define CIN3 (3*Cc)             // 192
#define IMG  (Cc*HW)            // 589824
#define NPIX (Bb*HW)            // 36864
#define NCH  27                 // K chunks of 64: K = k*192 + c (k-major)

// Scratch
__device__ float g_offset[Bb * 18 * HW];          // offset conv output
__device__ float4 g_mw[Bb * 9 * HW];              // bilinear weights per (b,k,pix)
__device__ int4   g_mi[Bb * 9 * HW];              // bilinear indices (plane-relative)
__device__ __nv_bfloat16 g_wh[NCH * 64 * 64];     // B tiles hi (pre-swizzled)
__device__ __nv_bfloat16 g_wl[NCH * 64 * 64];     // B tiles lo

// ---------------- helpers ----------------
__device__ __forceinline__ uint32_t smem_to_u32(const void* p) {
    uint32_t a;
    asm("{ .reg .u64 t; cvta.to.shared.u64 t, %1; cvt.u32.u64 %0, t; }"
        : "=r"(a) : "l"(p));
    return a;
}
__device__ __forceinline__ void ldsm_x4(uint32_t* r, uint32_t addr) {
    asm volatile("ldmatrix.sync.aligned.m8n8.x4.shared.b16 {%0,%1,%2,%3}, [%4];"
        : "=r"(r[0]), "=r"(r[1]), "=r"(r[2]), "=r"(r[3]) : "r"(addr));
}
__device__ __forceinline__ void ldsm_x4_t(uint32_t* r, uint32_t addr) {
    asm volatile("ldmatrix.sync.aligned.m8n8.x4.trans.shared.b16 {%0,%1,%2,%3}, [%4];"
        : "=r"(r[0]), "=r"(r[1]), "=r"(r[2]), "=r"(r[3]) : "r"(addr));
}
__device__ __forceinline__ void mma_bf16(float* d, const uint32_t* a,
                                         uint32_t b0, uint32_t b1) {
    asm volatile("mma.sync.aligned.m16n8k16.row.col.f32.bf16.bf16.f32 "
        "{%0,%1,%2,%3}, {%4,%5,%6,%7}, {%8,%9}, {%0,%1,%2,%3};"
        : "+f"(d[0]), "+f"(d[1]), "+f"(d[2]), "+f"(d[3])
        : "r"(a[0]), "r"(a[1]), "r"(a[2]), "r"(a[3]), "r"(b0), "r"(b1));
}

// ---------------------------------------------------------------------------
// Kernel 1: diff = (ref - dist)^2  (NCHW, second output tensor; also GEMM input)
// ---------------------------------------------------------------------------
__global__ void diff_kernel(const float* __restrict__ ref,
                            const float* __restrict__ dist,
                            float* __restrict__ out_diff) {
    int i = blockIdx.x * blockDim.x + threadIdx.x;
    if (i < Bb * IMG) {
        float d = ref[i] - dist[i];
        out_diff[i] = d * d;
    }
}

// ---------------------------------------------------------------------------
// Kernel 2: offset conv3x3 (Cin=64 -> 18)  [unchanged from round 1, passing]
// ---------------------------------------------------------------------------
__global__ __launch_bounds__(256) void offset_conv_kernel(
        const float* __restrict__ ref,
        const float* __restrict__ ow, const float* __restrict__ ob,
        float* __restrict__ out) {
    __shared__ __align__(16) float s_w[576 * 20];
    int tid = threadIdx.x;
    for (int i = tid; i < 18 * 576; i += 256) {
        int o = i / 576, ck = i % 576;
        s_w[ck * 20 + o] = ow[i];
    }
    __syncthreads();

    int p = blockIdx.x * 256 + tid;
    int b = p / HW;
    int pix = p % HW;
    int y = pix / Ww, x = pix % Ww;

    int  idx9[9]; bool ok9[9];
#pragma unroll
    for (int ky = 0; ky < 3; ky++)
#pragma unroll
        for (int kx = 0; kx < 3; kx++) {
            int yy = y + ky - 1, xx = x + kx - 1;
            bool ok = (yy >= 0) && (yy < Hh) && (xx >= 0) && (xx < Ww);
            ok9[ky * 3 + kx] = ok;
            idx9[ky * 3 + kx] = (ok ? yy : 0) * Ww + (ok ? xx : 0);
        }

    float acc[18];
#pragma unroll
    for (int o = 0; o < 18; o++) acc[o] = 0.f;

    const float* xb = ref + b * IMG;
    for (int c = 0; c < Cc; c++) {
        const float* xc = xb + c * HW;
#pragma unroll
        for (int k = 0; k < 9; k++) {
            float v = ok9[k] ? __ldg(xc + idx9[k]) : 0.f;
            int base = (c * 9 + k) * 20;
            float4 w0 = *(const float4*)&s_w[base];
            float4 w1 = *(const float4*)&s_w[base + 4];
            float4 w2 = *(const float4*)&s_w[base + 8];
            float4 w3 = *(const float4*)&s_w[base + 12];
            float  wa = s_w[base + 16];
            float  wb = s_w[base + 17];
            acc[0]  += v * w0.x;  acc[1]  += v * w0.y;  acc[2]  += v * w0.z;  acc[3]  += v * w0.w;
            acc[4]  += v * w1.x;  acc[5]  += v * w1.y;  acc[6]  += v * w1.z;  acc[7]  += v * w1.w;
            acc[8]  += v * w2.x;  acc[9]  += v * w2.y;  acc[10] += v * w2.z;  acc[11] += v * w2.w;
            acc[12] += v * w3.x;  acc[13] += v * w3.y;  acc[14] += v * w3.z;  acc[15] += v * w3.w;
            acc[16] += v * wa;    acc[17] += v * wb;
        }
    }
#pragma unroll
    for (int o = 0; o < 18; o++)
        out[(b * 18 + o) * HW + pix] = acc[o] + __ldg(ob + o);
}

// ---------------------------------------------------------------------------
// Kernel 3: bilinear meta from offsets: weights (float4) + indices (int4)
// ---------------------------------------------------------------------------
__global__ void meta_kernel(float4* __restrict__ mw, int4* __restrict__ mi) {
    int i = blockIdx.x * blockDim.x + threadIdx.x;
    if (i >= Bb * 9 * HW) return;
    int pix = i % HW;
    int k   = (i / HW) % 9;
    int b   = i / (9 * HW);
    int y = pix / Ww, x = pix % Ww;
    float offy = g_offset[(b * 18 + 2 * k)     * HW + pix];
    float offx = g_offset[(b * 18 + 2 * k + 1) * HW + pix];
    float py = (float)(y - 1 + k / 3) + offy;
    float px = (float)(x - 1 + k % 3) + offx;
    float fy = floorf(py), fx = floorf(px);
    int y0 = (int)fy, x0 = (int)fx;
    float dy = py - fy, dx = px - fx;
    float wv[4]; int iv[4];
#pragma unroll
    for (int t = 0; t < 4; t++) {
        int yt = y0 + (t >> 1);
        int xt = x0 + (t & 1);
        float wt = ((t >> 1) ? dy : (1.f - dy)) * ((t & 1) ? dx : (1.f - dx));
        bool valid = (yt >= 0) && (yt < Hh) && (xt >= 0) && (xt < Ww);
        int yc = yt < 0 ? 0 : (yt > Hh - 1 ? Hh - 1 : yt);
        int xc = xt < 0 ? 0 : (xt > Ww - 1 ? Ww - 1 : xt);
        wv[t] = valid ? wt : 0.f;
        iv[t] = yc * Ww + xc;
    }
    mw[i] = make_float4(wv[0], wv[1], wv[2], wv[3]);
    mi[i] = make_int4(iv[0], iv[1], iv[2], iv[3]);
}

// ---------------------------------------------------------------------------
// Kernel 4: weight prep -> bf16 hi/lo B tiles, XOR-swizzled [n][k] layout.
// Chunk ch: tap k = ch/3, channels cg = (ch%3)*64 + c.  Row n (=o): 128B,
// 16B chunk index kc=c>>3 stored at kc^(n&7).
// ---------------------------------------------------------------------------
__global__ void wprep_kernel(const float* __restrict__ dw,
                             __nv_bfloat16* __restrict__ wh,
                             __nv_bfloat16* __restrict__ wl) {
    int i = blockIdx.x * blockDim.x + threadIdx.x;
    if (i >= NCH * 64 * 64) return;
    int c  = i & 63;
    int o  = (i >> 6) & 63;
    int ch = i >> 12;
    int k  = ch / 3;
    int cg = (ch % 3) * 64 + c;
    float v = __ldg(dw + o * (CIN3 * 9) + cg * 9 + k);
    __nv_bfloat16 hi = __float2bfloat16(v);
    __nv_bfloat16 lo = __float2bfloat16(v - __bfloat162float(hi));
    int elem = o * 64 + (((c >> 3) ^ (o & 7)) << 3) + (c & 7);
    wh[ch * 4096 + elem] = hi;
    wl[ch * 4096 + elem] = lo;
}

// ---------------------------------------------------------------------------
// Kernel 5: deformable conv via mma.sync bf16 hi/lo split.
// Block: M=128 px, N=64 out, 256 threads (8 warps: 4 m-warps x 2 n-warps,
// warp tile 32x32).  27 chunks (tap k, 64 channels); 4 k16 steps per chunk.
// smem: A_hi[64][272B rows] 17408 | A_lo 17408 | B_hi[64][128B] 8192 | B_lo 8192
// ---------------------------------------------------------------------------
#define SM_AH 0
#define SM_AL 17408
#define SM_BH 34816
#define SM_BL 43008
#define SM_TOTAL 51200

__global__ __launch_bounds__(256, 2) void deform_kernel(
        const float* __restrict__ ref, const float* __restrict__ dist,
        const float* __restrict__ diffp,
        const float4* __restrict__ mw, const int4* __restrict__ mi,
        const __nv_bfloat16* __restrict__ wh, const __nv_bfloat16* __restrict__ wl,
        const float* __restrict__ db, float* __restrict__ out) {
    extern __shared__ char smem[];
    uint32_t sb = smem_to_u32(smem);

    int tid  = threadIdx.x;
    int lane = tid & 31;
    int warp = tid >> 5;
    int b    = blockIdx.x / 72;
    int pix0 = (blockIdx.x % 72) * 128;

    // A-build assignment: p fixed per thread, channel half by tid>>7
    int p      = tid & 127;
    int chalf  = tid >> 7;           // 0 or 1 -> channels 0-31 / 32-63

    // warp GEMM tile
    int m0 = (warp & 3) * 32;
    int n0 = (warp >> 2) * 32;

    const float* srcs[3];
    srcs[0] = ref   + b * IMG;
    srcs[1] = dist  + b * IMG;
    srcs[2] = diffp + b * IMG;

    float acc[2][4][4];
#pragma unroll
    for (int i = 0; i < 2; i++)
#pragma unroll
        for (int j = 0; j < 4; j++)
#pragma unroll
            for (int q = 0; q < 4; q++) acc[i][j][q] = 0.f;

    // precompute lane-dependent ldmatrix address parts
    //   A (.x4.trans on [k][m], 272B rows):
    uint32_t a_row = ((lane >> 4) << 3) + (lane & 7);        // + k0
    uint32_t a_col = ((lane >> 3) & 1) << 3;                 // + m0(+16*mi)
    //   B (.x4 on [n][k-swizzled], 128B rows):
    uint32_t b_n   = ((lane >> 4) << 3) + (lane & 7);        // + n0 + 16*g
    uint32_t b_kc  = (lane >> 3) & 1;                        // + k0/8

    float4 wgt = make_float4(0, 0, 0, 0);
    int4   idx = make_int4(0, 0, 0, 0);
    int curk = -1;

    for (int ch = 0; ch < NCH; ch++) {
        int k   = ch / 3;
        int cbl = ch % 3;
        if (k != curk) {
            curk = k;
            wgt = __ldg(mw + (b * 9 + k) * HW + pix0 + p);
            idx = __ldg(mi + (b * 9 + k) * HW + pix0 + p);
        }
        __syncthreads();   // prior GEMM finished reading smem
        // ---- stage B (pre-swizzled, straight copy) ----
        {
            const float4* s1 = (const float4*)(wh + ch * 4096);
            const float4* s2 = (const float4*)(wl + ch * 4096);
            float4* d1 = (float4*)(smem + SM_BH);
            float4* d2 = (float4*)(smem + SM_BL);
            for (int i = tid; i < 512; i += 256) {
                d1[i] = __ldg(s1 + i);
                d2[i] = __ldg(s2 + i);
            }
        }
        // ---- build A: 32 channels per thread, coalesced NCHW gather ----
        {
            const float* src = srcs[cbl] + (size_t)(chalf * 32) * HW;
#pragma unroll 4
            for (int j = 0; j < 32; j++) {
                const float* pl = src + (size_t)j * HW;
                float v = wgt.x * __ldg(pl + idx.x) + wgt.y * __ldg(pl + idx.y)
                        + wgt.z * __ldg(pl + idx.z) + wgt.w * __ldg(pl + idx.w);
                __nv_bfloat16 h = __float2bfloat16(v);
                __nv_bfloat16 l = __float2bfloat16(v - __bfloat162float(h));
                int c = chalf * 32 + j;
                ((__nv_bfloat16*)(smem + SM_AH + c * 272))[p] = h;
                ((__nv_bfloat16*)(smem + SM_AL + c * 272))[p] = l;
            }
        }
        __syncthreads();
        // ---- GEMM: 4 k16 steps ----
#pragma unroll
        for (int ks = 0; ks < 4; ks++) {
            uint32_t k0 = ks * 16;
            uint32_t ah[2][4], al[2][4], bh[2][4], bl[2][4];
#pragma unroll
            for (int mi_ = 0; mi_ < 2; mi_++) {
                uint32_t aoff = (k0 + a_row) * 272 + (m0 + mi_ * 16 + a_col) * 2;
                ldsm_x4_t(ah[mi_], sb + SM_AH + aoff);
                ldsm_x4_t(al[mi_], sb + SM_AL + aoff);
            }
#pragma unroll
            for (int g = 0; g < 2; g++) {
                uint32_t n  = n0 + g * 16 + b_n;
                uint32_t kc = (k0 >> 3) + b_kc;
                uint32_t boff = n * 128 + ((kc ^ (n & 7)) << 4);
                ldsm_x4(bh[g], sb + SM_BH + boff);
                ldsm_x4(bl[g], sb + SM_BL + boff);
            }
#pragma unroll
            for (int mi_ = 0; mi_ < 2; mi_++)
#pragma unroll
                for (int g = 0; g < 2; g++)
#pragma unroll
                    for (int s = 0; s < 2; s++) {
                        int ni = g * 2 + s;
                        mma_bf16(acc[mi_][ni], ah[mi_], bh[g][2 * s], bh[g][2 * s + 1]);
                        mma_bf16(acc[mi_][ni], ah[mi_], bl[g][2 * s], bl[g][2 * s + 1]);
                        mma_bf16(acc[mi_][ni], al[mi_], bh[g][2 * s], bh[g][2 * s + 1]);
                    }
        }
    }

    // ---- epilogue: bias + relu ----
    int r  = lane >> 2;
    int cp = (lane & 3) * 2;
#pragma unroll
    for (int mi_ = 0; mi_ < 2; mi_++) {
        int pixb = pix0 + m0 + mi_ * 16 + r;
#pragma unroll
        for (int ni = 0; ni < 4; ni++) {
            int o = n0 + ni * 8 + cp;
            float b0v = __ldg(db + o);
            float b1v = __ldg(db + o + 1);
            float* o0 = out + (size_t)(b * Oo + o) * HW;
            float* o1 = out + (size_t)(b * Oo + o + 1) * HW;
            float v;
            v = acc[mi_][ni][0] + b0v; o0[pixb]     = v > 0.f ? v : 0.f;
            v = acc[mi_][ni][1] + b1v; o1[pixb]     = v > 0.f ? v : 0.f;
            v = acc[mi_][ni][2] + b0v; o0[pixb + 8] = v > 0.f ? v : 0.f;
            v = acc[mi_][ni][3] + b1v; o1[pixb + 8] = v > 0.f ? v : 0.f;
        }
    }
}

// ---------------------------------------------------------------------------
extern "C" void kernel_launch(void* const* d_in, const int* in_sizes, int n_in,
                              void* d_out, int out_size) {
    const float* ref  = (const float*)d_in[0];
    const float* dist = (const float*)d_in[1];
    const float* ow   = (const float*)d_in[2];
    const float* ob   = (const float*)d_in[3];
    const float* dw   = (const float*)d_in[4];
    const float* db   = (const float*)d_in[5];
    float* out = (float*)d_out;
    float* out_feat = out;
    float* out_diff = out + Bb * IMG;

    float* offbuf;  cudaGetSymbolAddress((void**)&offbuf, g_offset);
    float4* mw;     cudaGetSymbolAddress((void**)&mw, g_mw);
    int4*   mi;     cudaGetSymbolAddress((void**)&mi, g_mi);
    __nv_bfloat16* wh; cudaGetSymbolAddress((void**)&wh, g_wh);
    __nv_bfloat16* wl; cudaGetSymbolAddress((void**)&wl, g_wl);

    cudaFuncSetAttribute(deform_kernel,
                         cudaFuncAttributeMaxDynamicSharedMemorySize, SM_TOTAL);

    diff_kernel<<<(Bb * IMG + 255) / 256, 256>>>(ref, dist, out_diff);
    offset_conv_kernel<<<NPIX / 256, 256>>>(ref, ow, ob, offbuf);
    meta_kernel<<<(Bb * 9 * HW + 255) / 256, 256>>>(mw, mi);
    wprep_kernel<<<(NCH * 64 * 64 + 255) / 256, 256>>>(dw, wh, wl);
    deform_kernel<<<NPIX / 128, 256, SM_TOTAL>>>(ref, dist, out_diff,
                                                 mw, mi, wh, wl, db, out_feat);
}

// round 5
// speedup vs baseline: 2.4947x; 1.1880x over previous
#include <cuda_runtime.h>
#include <cuda_bf16.h>
#include <math.h>
#include <stdint.h>

// Problem constants
#define Bb   4
#define Cc   64
#define Hh   96
#define Ww   96
#define HW   (Hh*Ww)            // 9216
#define Oo   64
#define CIN3 (3*Cc)             // 192
#define IMG  (Cc*HW)            // 589824
#define NPIX (Bb*HW)            // 36864
#define NCH  27                 // K chunks of 64: K = k*192 + c (k-major)

// Scratch
__device__ float g_offset[Bb * 18 * HW];
__device__ float4 g_mw[Bb * 9 * HW];
__device__ int4   g_mi[Bb * 9 * HW];
__device__ __nv_bfloat16 g_wh[NCH * 64 * 64];     // B tiles hi (pre-swizzled)
__device__ __nv_bfloat16 g_wl[NCH * 64 * 64];     // B tiles lo

// ---------------- helpers ----------------
__device__ __forceinline__ uint32_t smem_to_u32(const void* p) {
    uint32_t a;
    asm("{ .reg .u64 t; cvta.to.shared.u64 t, %1; cvt.u32.u64 %0, t; }"
        : "=r"(a) : "l"(p));
    return a;
}
__device__ __forceinline__ void ldsm_x4(uint32_t* r, uint32_t addr) {
    asm volatile("ldmatrix.sync.aligned.m8n8.x4.shared.b16 {%0,%1,%2,%3}, [%4];"
        : "=r"(r[0]), "=r"(r[1]), "=r"(r[2]), "=r"(r[3]) : "r"(addr));
}
__device__ __forceinline__ void mma_bf16(float* d, const uint32_t* a,
                                         uint32_t b0, uint32_t b1) {
    asm volatile("mma.sync.aligned.m16n8k16.row.col.f32.bf16.bf16.f32 "
        "{%0,%1,%2,%3}, {%4,%5,%6,%7}, {%8,%9}, {%0,%1,%2,%3};"
        : "+f"(d[0]), "+f"(d[1]), "+f"(d[2]), "+f"(d[3])
        : "r"(a[0]), "r"(a[1]), "r"(a[2]), "r"(a[3]), "r"(b0), "r"(b1));
}
__device__ __forceinline__ void cp_async16(uint32_t smem_addr, const void* gptr) {
    asm volatile("cp.async.cg.shared.global [%0], [%1], 16;"
        :: "r"(smem_addr), "l"(gptr));
}
#define CP_COMMIT() asm volatile("cp.async.commit_group;" ::: "memory")
#define CP_WAIT0()  asm volatile("cp.async.wait_group 0;" ::: "memory")

// ---------------------------------------------------------------------------
// Kernel 1: diff = (ref - dist)^2
// ---------------------------------------------------------------------------
__global__ void diff_kernel(const float* __restrict__ ref,
                            const float* __restrict__ dist,
                            float* __restrict__ out_diff) {
    int i = blockIdx.x * blockDim.x + threadIdx.x;
    if (i < Bb * IMG) {
        float d = ref[i] - dist[i];
        out_diff[i] = d * d;
    }
}

// ---------------------------------------------------------------------------
// Kernel 2: offset conv3x3 (Cin=64 -> 18)
// ---------------------------------------------------------------------------
__global__ __launch_bounds__(256) void offset_conv_kernel(
        const float* __restrict__ ref,
        const float* __restrict__ ow, const float* __restrict__ ob,
        float* __restrict__ out) {
    __shared__ __align__(16) float s_w[576 * 20];
    int tid = threadIdx.x;
    for (int i = tid; i < 18 * 576; i += 256) {
        int o = i / 576, ck = i % 576;
        s_w[ck * 20 + o] = ow[i];
    }
    __syncthreads();

    int p = blockIdx.x * 256 + tid;
    int b = p / HW;
    int pix = p % HW;
    int y = pix / Ww, x = pix % Ww;

    int  idx9[9]; bool ok9[9];
#pragma unroll
    for (int ky = 0; ky < 3; ky++)
#pragma unroll
        for (int kx = 0; kx < 3; kx++) {
            int yy = y + ky - 1, xx = x + kx - 1;
            bool ok = (yy >= 0) && (yy < Hh) && (xx >= 0) && (xx < Ww);
            ok9[ky * 3 + kx] = ok;
            idx9[ky * 3 + kx] = (ok ? yy : 0) * Ww + (ok ? xx : 0);
        }

    float acc[18];
#pragma unroll
    for (int o = 0; o < 18; o++) acc[o] = 0.f;

    const float* xb = ref + b * IMG;
    for (int c = 0; c < Cc; c++) {
        const float* xc = xb + c * HW;
#pragma unroll
        for (int k = 0; k < 9; k++) {
            float v = ok9[k] ? __ldg(xc + idx9[k]) : 0.f;
            int base = (c * 9 + k) * 20;
            float4 w0 = *(const float4*)&s_w[base];
            float4 w1 = *(const float4*)&s_w[base + 4];
            float4 w2 = *(const float4*)&s_w[base + 8];
            float4 w3 = *(const float4*)&s_w[base + 12];
            float  wa = s_w[base + 16];
            float  wb = s_w[base + 17];
            acc[0]  += v * w0.x;  acc[1]  += v * w0.y;  acc[2]  += v * w0.z;  acc[3]  += v * w0.w;
            acc[4]  += v * w1.x;  acc[5]  += v * w1.y;  acc[6]  += v * w1.z;  acc[7]  += v * w1.w;
            acc[8]  += v * w2.x;  acc[9]  += v * w2.y;  acc[10] += v * w2.z;  acc[11] += v * w2.w;
            acc[12] += v * w3.x;  acc[13] += v * w3.y;  acc[14] += v * w3.z;  acc[15] += v * w3.w;
            acc[16] += v * wa;    acc[17] += v * wb;
        }
    }
#pragma unroll
    for (int o = 0; o < 18; o++)
        out[(b * 18 + o) * HW + pix] = acc[o] + __ldg(ob + o);
}

// ---------------------------------------------------------------------------
// Kernel 3: bilinear meta
// ---------------------------------------------------------------------------
__global__ void meta_kernel(float4* __restrict__ mw, int4* __restrict__ mi) {
    int i = blockIdx.x * blockDim.x + threadIdx.x;
    if (i >= Bb * 9 * HW) return;
    int pix = i % HW;
    int k   = (i / HW) % 9;
    int b   = i / (9 * HW);
    int y = pix / Ww, x = pix % Ww;
    float offy = g_offset[(b * 18 + 2 * k)     * HW + pix];
    float offx = g_offset[(b * 18 + 2 * k + 1) * HW + pix];
    float py = (float)(y - 1 + k / 3) + offy;
    float px = (float)(x - 1 + k % 3) + offx;
    float fy = floorf(py), fx = floorf(px);
    int y0 = (int)fy, x0 = (int)fx;
    float dy = py - fy, dx = px - fx;
    float wv[4]; int iv[4];
#pragma unroll
    for (int t = 0; t < 4; t++) {
        int yt = y0 + (t >> 1);
        int xt = x0 + (t & 1);
        float wt = ((t >> 1) ? dy : (1.f - dy)) * ((t & 1) ? dx : (1.f - dx));
        bool valid = (yt >= 0) && (yt < Hh) && (xt >= 0) && (xt < Ww);
        int yc = yt < 0 ? 0 : (yt > Hh - 1 ? Hh - 1 : yt);
        int xc = xt < 0 ? 0 : (xt > Ww - 1 ? Ww - 1 : xt);
        wv[t] = valid ? wt : 0.f;
        iv[t] = yc * Ww + xc;
    }
    mw[i] = make_float4(wv[0], wv[1], wv[2], wv[3]);
    mi[i] = make_int4(iv[0], iv[1], iv[2], iv[3]);
}

// ---------------------------------------------------------------------------
// Kernel 4: weight prep -> bf16 hi/lo B tiles, XOR-swizzled [n][k] layout
// ---------------------------------------------------------------------------
__global__ void wprep_kernel(const float* __restrict__ dw,
                             __nv_bfloat16* __restrict__ wh,
                             __nv_bfloat16* __restrict__ wl) {
    int i = blockIdx.x * blockDim.x + threadIdx.x;
    if (i >= NCH * 64 * 64) return;
    int c  = i & 63;
    int o  = (i >> 6) & 63;
    int ch = i >> 12;
    int k  = ch / 3;
    int cg = (ch % 3) * 64 + c;
    float v = __ldg(dw + o * (CIN3 * 9) + cg * 9 + k);
    __nv_bfloat16 hi = __float2bfloat16(v);
    __nv_bfloat16 lo = __float2bfloat16(v - __bfloat162float(hi));
    int elem = o * 64 + (((c >> 3) ^ (o & 7)) << 3) + (c & 7);
    wh[ch * 4096 + elem] = hi;
    wl[ch * 4096 + elem] = lo;
}

// ---------------------------------------------------------------------------
// Kernel 5: deformable conv, mma.sync bf16 hi/lo, double-buffered pipeline.
// A tile layout: [p][64 ch], 128B rows, 16B chunks XOR-swizzled by (p&7).
// Per buffer (48KB): A_hi@0 16K | A_lo@16K 16K | B_hi@32K 8K | B_lo@40K 8K
// ---------------------------------------------------------------------------
#define SM_BUF   49152
#define SM_AHOF  0
#define SM_ALOF  16384
#define SM_BHOF  32768
#define SM_BLOF  40960
#define SM_TOTAL (2 * SM_BUF)

__global__ __launch_bounds__(256, 2) void deform_kernel(
        const float* __restrict__ ref, const float* __restrict__ dist,
        const float* __restrict__ diffp,
        const float4* __restrict__ mw, const int4* __restrict__ mi,
        const __nv_bfloat16* __restrict__ wh, const __nv_bfloat16* __restrict__ wl,
        const float* __restrict__ db, float* __restrict__ out) {
    extern __shared__ char smem[];
    uint32_t sb = smem_to_u32(smem);

    int tid  = threadIdx.x;
    int lane = tid & 31;
    int warp = tid >> 5;
    int b    = blockIdx.x / 72;
    int pix0 = (blockIdx.x % 72) * 128;

    // A-build assignment: pixel p, channel half
    int p     = tid & 127;
    int chalf = tid >> 7;            // 0/1 -> channels 0-31 / 32-63
    uint32_t a_sts = (uint32_t)p * 128;   // row base (bytes)

    // warp GEMM tile
    int m0 = (warp & 3) * 32;
    int n0 = (warp >> 2) * 32;

    const float* srcs[3];
    srcs[0] = ref   + b * IMG;
    srcs[1] = dist  + b * IMG;
    srcs[2] = diffp + b * IMG;

    float acc[2][4][4];
#pragma unroll
    for (int i = 0; i < 2; i++)
#pragma unroll
        for (int j = 0; j < 4; j++)
#pragma unroll
            for (int q = 0; q < 4; q++) acc[i][j][q] = 0.f;

    // ldmatrix lane addressing
    uint32_t a_m  = lane & 15;                 // row within 16 (+ m0 + 16*mi)
    uint32_t a_kc = lane >> 4;                 // +2*ks
    uint32_t b_n  = ((lane >> 4) << 3) + (lane & 7);
    uint32_t b_kc = (lane >> 3) & 1;

    // B cp.async assignment: 512 x 16B per tile, 2 per thread per tile
    int bcp0 = tid, bcp1 = tid + 256;

    // ---------- build(): gather + cvt + STS for one chunk ----------
    auto build = [&](int ch) {
        int k   = ch / 3;
        int cbl = ch - 3 * k;
        float4 wgt = __ldg(mw + (b * 9 + k) * HW + pix0 + p);
        int4   idx = __ldg(mi + (b * 9 + k) * HW + pix0 + p);
        const float* src = srcs[cbl] + (size_t)(chalf * 32) * HW;
        char* bufc = smem + (ch & 1) * SM_BUF;
#pragma unroll
        for (int q = 0; q < 4; q++) {
            float v[8];
#pragma unroll
            for (int j = 0; j < 8; j++) {
                const float* pl = src + (size_t)(q * 8 + j) * HW;
                v[j] = wgt.x * __ldg(pl + idx.x) + wgt.y * __ldg(pl + idx.y)
                     + wgt.z * __ldg(pl + idx.z) + wgt.w * __ldg(pl + idx.w);
            }
            uint32_t hp[4], lp[4];
#pragma unroll
            for (int jj = 0; jj < 4; jj++) {
                __nv_bfloat162 hb = __float22bfloat162_rn(
                    make_float2(v[2 * jj], v[2 * jj + 1]));
                hp[jj] = *(uint32_t*)&hb;
                float r0 = v[2 * jj]     - __bfloat162float(hb.x);
                float r1 = v[2 * jj + 1] - __bfloat162float(hb.y);
                __nv_bfloat162 lb = __float22bfloat162_rn(make_float2(r0, r1));
                lp[jj] = *(uint32_t*)&lb;
            }
            int kc = chalf * 4 + q;
            uint32_t off = a_sts + (uint32_t)((kc ^ (p & 7)) << 4);
            *(uint4*)(bufc + SM_AHOF + off) = make_uint4(hp[0], hp[1], hp[2], hp[3]);
            *(uint4*)(bufc + SM_ALOF + off) = make_uint4(lp[0], lp[1], lp[2], lp[3]);
        }
    };

    // ---------- stage_B(): cp.async 16KB of pre-swizzled B ----------
    auto stage_B = [&](int ch) {
        uint32_t bufb = sb + (ch & 1) * SM_BUF;
        const char* gh = (const char*)(wh + ch * 4096);
        const char* gl = (const char*)(wl + ch * 4096);
        cp_async16(bufb + SM_BHOF + bcp0 * 16, gh + bcp0 * 16);
        cp_async16(bufb + SM_BHOF + bcp1 * 16, gh + bcp1 * 16);
        cp_async16(bufb + SM_BLOF + bcp0 * 16, gl + bcp0 * 16);
        cp_async16(bufb + SM_BLOF + bcp1 * 16, gl + bcp1 * 16);
        CP_COMMIT();
    };

    // ---------- prologue: chunk 0 ----------
    stage_B(0);
    build(0);
    CP_WAIT0();
    __syncthreads();

    for (int ch = 0; ch < NCH; ch++) {
        int nxt = ch + 1;
        if (nxt < NCH) stage_B(nxt);

        // ---- GEMM on buf[ch&1]: 4 k16 steps ----
        uint32_t bufb = sb + (ch & 1) * SM_BUF;
#pragma unroll
        for (int ks = 0; ks < 4; ks++) {
            uint32_t ah[2][4], al[2][4], bh[2][4], bl[2][4];
#pragma unroll
            for (int mi_ = 0; mi_ < 2; mi_++) {
                uint32_t row = m0 + mi_ * 16 + a_m;
                uint32_t aoff = row * 128 + ((((ks << 1) + a_kc) ^ (row & 7)) << 4);
                ldsm_x4(ah[mi_], bufb + SM_AHOF + aoff);
                ldsm_x4(al[mi_], bufb + SM_ALOF + aoff);
            }
#pragma unroll
            for (int g = 0; g < 2; g++) {
                uint32_t n  = n0 + g * 16 + b_n;
                uint32_t kc = (ks << 1) + b_kc;
                uint32_t boff = n * 128 + ((kc ^ (n & 7)) << 4);
                ldsm_x4(bh[g], bufb + SM_BHOF + boff);
                ldsm_x4(bl[g], bufb + SM_BLOF + boff);
            }
#pragma unroll
            for (int mi_ = 0; mi_ < 2; mi_++)
#pragma unroll
                for (int g = 0; g < 2; g++)
#pragma unroll
                    for (int s = 0; s < 2; s++) {
                        int ni = g * 2 + s;
                        mma_bf16(acc[mi_][ni], ah[mi_], bh[g][2 * s], bh[g][2 * s + 1]);
                        mma_bf16(acc[mi_][ni], ah[mi_], bl[g][2 * s], bl[g][2 * s + 1]);
                        mma_bf16(acc[mi_][ni], al[mi_], bh[g][2 * s], bh[g][2 * s + 1]);
                    }
        }

        if (nxt < NCH) build(nxt);
        CP_WAIT0();
        __syncthreads();
    }

    // ---- epilogue: bias + relu ----
    int r  = lane >> 2;
    int cp = (lane & 3) * 2;
#pragma unroll
    for (int mi_ = 0; mi_ < 2; mi_++) {
        int pixb = pix0 + m0 + mi_ * 16 + r;
#pragma unroll
        for (int ni = 0; ni < 4; ni++) {
            int o = n0 + ni * 8 + cp;
            float b0v = __ldg(db + o);
            float b1v = __ldg(db + o + 1);
            float* o0 = out + (size_t)(b * Oo + o) * HW;
            float* o1 = out + (size_t)(b * Oo + o + 1) * HW;
            float v;
            v = acc[mi_][ni][0] + b0v; o0[pixb]     = v > 0.f ? v : 0.f;
            v = acc[mi_][ni][1] + b1v; o1[pixb]     = v > 0.f ? v : 0.f;
            v = acc[mi_][ni][2] + b0v; o0[pixb + 8] = v > 0.f ? v : 0.f;
            v = acc[mi_][ni][3] + b1v; o1[pixb + 8] = v > 0.f ? v : 0.f;
        }
    }
}

// ---------------------------------------------------------------------------
extern "C" void kernel_launch(void* const* d_in, const int* in_sizes, int n_in,
                              void* d_out, int out_size) {
    const float* ref  = (const float*)d_in[0];
    const float* dist = (const float*)d_in[1];
    const float* ow   = (const float*)d_in[2];
    const float* ob   = (const float*)d_in[3];
    const float* dw   = (const float*)d_in[4];
    const float* db   = (const float*)d_in[5];
    float* out = (float*)d_out;
    float* out_feat = out;
    float* out_diff = out + Bb * IMG;

    float* offbuf;  cudaGetSymbolAddress((void**)&offbuf, g_offset);
    float4* mw;     cudaGetSymbolAddress((void**)&mw, g_mw);
    int4*   mi;     cudaGetSymbolAddress((void**)&mi, g_mi);
    __nv_bfloat16* wh; cudaGetSymbolAddress((void**)&wh, g_wh);
    __nv_bfloat16* wl; cudaGetSymbolAddress((void**)&wl, g_wl);

    cudaFuncSetAttribute(deform_kernel,
                         cudaFuncAttributeMaxDynamicSharedMemorySize, SM_TOTAL);

    diff_kernel<<<(Bb * IMG + 255) / 256, 256>>>(ref, dist, out_diff);
    offset_conv_kernel<<<NPIX / 256, 256>>>(ref, ow, ob, offbuf);
    meta_kernel<<<(Bb * 9 * HW + 255) / 256, 256>>>(mw, mi);
    wprep_kernel<<<(NCH * 64 * 64 + 255) / 256, 256>>>(dw, wh, wl);
    deform_kernel<<<NPIX / 128, 256, SM_TOTAL>>>(ref, dist, out_diff,
                                                 mw, mi, wh, wl, db, out_feat);
}

// round 6
// speedup vs baseline: 2.5808x; 1.0345x over previous
#include <cuda_runtime.h>
#include <cuda_bf16.h>
#include <math.h>
#include <stdint.h>

// Problem constants
#define Bb   4
#define Cc   64
#define Hh   96
#define Ww   96
#define HW   (Hh*Ww)            // 9216
#define Oo   64
#define CIN3 (3*Cc)             // 192
#define IMG  (Cc*HW)            // 589824
#define NPIX (Bb*HW)            // 36864
#define NCH  27                 // K chunks of 64: K = k*192 + c (k-major)

// Scratch
__device__ float4 g_mw[Bb * 9 * HW];
__device__ int4   g_mi[Bb * 9 * HW];
__device__ __nv_bfloat16 g_wh[NCH * 64 * 64];     // B tiles hi (pre-swizzled)
__device__ __nv_bfloat16 g_wl[NCH * 64 * 64];     // B tiles lo

// ---------------- helpers ----------------
__device__ __forceinline__ uint32_t smem_to_u32(const void* p) {
    uint32_t a;
    asm("{ .reg .u64 t; cvta.to.shared.u64 t, %1; cvt.u32.u64 %0, t; }"
        : "=r"(a) : "l"(p));
    return a;
}
__device__ __forceinline__ void ldsm_x4(uint32_t* r, uint32_t addr) {
    asm volatile("ldmatrix.sync.aligned.m8n8.x4.shared.b16 {%0,%1,%2,%3}, [%4];"
        : "=r"(r[0]), "=r"(r[1]), "=r"(r[2]), "=r"(r[3]) : "r"(addr));
}
__device__ __forceinline__ void mma_bf16(float* d, const uint32_t* a,
                                         uint32_t b0, uint32_t b1) {
    asm volatile("mma.sync.aligned.m16n8k16.row.col.f32.bf16.bf16.f32 "
        "{%0,%1,%2,%3}, {%4,%5,%6,%7}, {%8,%9}, {%0,%1,%2,%3};"
        : "+f"(d[0]), "+f"(d[1]), "+f"(d[2]), "+f"(d[3])
        : "r"(a[0]), "r"(a[1]), "r"(a[2]), "r"(a[3]), "r"(b0), "r"(b1));
}
__device__ __forceinline__ void cp_async16(uint32_t smem_addr, const void* gptr) {
    asm volatile("cp.async.cg.shared.global [%0], [%1], 16;"
        :: "r"(smem_addr), "l"(gptr));
}
#define CP_COMMIT() asm volatile("cp.async.commit_group;" ::: "memory")
#define CP_WAIT0()  asm volatile("cp.async.wait_group 0;" ::: "memory")

// ---------------------------------------------------------------------------
// Kernel 1: diff = (ref - dist)^2
// ---------------------------------------------------------------------------
__global__ void diff_kernel(const float* __restrict__ ref,
                            const float* __restrict__ dist,
                            float* __restrict__ out_diff) {
    int i = blockIdx.x * blockDim.x + threadIdx.x;
    if (i < Bb * IMG) {
        float d = ref[i] - dist[i];
        out_diff[i] = d * d;
    }
}

// ---------------------------------------------------------------------------
// Kernel 2: offset conv3x3 (Cin=64 -> 18) FUSED with bilinear meta computation.
// 288 blocks x 128 threads (one pixel per thread, 2 blocks/SM).
// ---------------------------------------------------------------------------
__global__ __launch_bounds__(128) void offset_meta_kernel(
        const float* __restrict__ ref,
        const float* __restrict__ ow, const float* __restrict__ ob,
        float4* __restrict__ mw, int4* __restrict__ mi) {
    __shared__ __align__(16) float s_w[576 * 20];
    int tid = threadIdx.x;
    for (int i = tid; i < 18 * 576; i += 128) {
        int o = i / 576, ck = i % 576;
        s_w[ck * 20 + o] = ow[i];
    }
    __syncthreads();

    int p = blockIdx.x * 128 + tid;
    int b = p / HW;
    int pix = p % HW;
    int y = pix / Ww, x = pix % Ww;

    int  idx9[9]; bool ok9[9];
#pragma unroll
    for (int ky = 0; ky < 3; ky++)
#pragma unroll
        for (int kx = 0; kx < 3; kx++) {
            int yy = y + ky - 1, xx = x + kx - 1;
            bool ok = (yy >= 0) && (yy < Hh) && (xx >= 0) && (xx < Ww);
            ok9[ky * 3 + kx] = ok;
            idx9[ky * 3 + kx] = (ok ? yy : 0) * Ww + (ok ? xx : 0);
        }

    float acc[18];
#pragma unroll
    for (int o = 0; o < 18; o++) acc[o] = 0.f;

    const float* xb = ref + b * IMG;
    for (int c = 0; c < Cc; c++) {
        const float* xc = xb + c * HW;
#pragma unroll
        for (int k = 0; k < 9; k++) {
            float v = ok9[k] ? __ldg(xc + idx9[k]) : 0.f;
            int base = (c * 9 + k) * 20;
            float4 w0 = *(const float4*)&s_w[base];
            float4 w1 = *(const float4*)&s_w[base + 4];
            float4 w2 = *(const float4*)&s_w[base + 8];
            float4 w3 = *(const float4*)&s_w[base + 12];
            float  wa = s_w[base + 16];
            float  wb = s_w[base + 17];
            acc[0]  += v * w0.x;  acc[1]  += v * w0.y;  acc[2]  += v * w0.z;  acc[3]  += v * w0.w;
            acc[4]  += v * w1.x;  acc[5]  += v * w1.y;  acc[6]  += v * w1.z;  acc[7]  += v * w1.w;
            acc[8]  += v * w2.x;  acc[9]  += v * w2.y;  acc[10] += v * w2.z;  acc[11] += v * w2.w;
            acc[12] += v * w3.x;  acc[13] += v * w3.y;  acc[14] += v * w3.z;  acc[15] += v * w3.w;
            acc[16] += v * wa;    acc[17] += v * wb;
        }
    }

    // ---- fused bilinear meta ----
#pragma unroll
    for (int k = 0; k < 9; k++) {
        float offy = acc[2 * k]     + __ldg(ob + 2 * k);
        float offx = acc[2 * k + 1] + __ldg(ob + 2 * k + 1);
        float py = (float)(y - 1 + k / 3) + offy;
        float px = (float)(x - 1 + k % 3) + offx;
        float fy = floorf(py), fx = floorf(px);
        int y0 = (int)fy, x0 = (int)fx;
        float dy = py - fy, dx = px - fx;
        float wv[4]; int iv[4];
#pragma unroll
        for (int t = 0; t < 4; t++) {
            int yt = y0 + (t >> 1);
            int xt = x0 + (t & 1);
            float wt = ((t >> 1) ? dy : (1.f - dy)) * ((t & 1) ? dx : (1.f - dx));
            bool valid = (yt >= 0) && (yt < Hh) && (xt >= 0) && (xt < Ww);
            int yc = yt < 0 ? 0 : (yt > Hh - 1 ? Hh - 1 : yt);
            int xc = xt < 0 ? 0 : (xt > Ww - 1 ? Ww - 1 : xt);
            wv[t] = valid ? wt : 0.f;
            iv[t] = yc * Ww + xc;
        }
        int mo = (b * 9 + k) * HW + pix;
        mw[mo] = make_float4(wv[0], wv[1], wv[2], wv[3]);
        mi[mo] = make_int4(iv[0], iv[1], iv[2], iv[3]);
    }
}

// ---------------------------------------------------------------------------
// Kernel 3: weight prep -> bf16 hi/lo B tiles, XOR-swizzled [n][k] layout
// ---------------------------------------------------------------------------
__global__ void wprep_kernel(const float* __restrict__ dw,
                             __nv_bfloat16* __restrict__ wh,
                             __nv_bfloat16* __restrict__ wl) {
    int i = blockIdx.x * blockDim.x + threadIdx.x;
    if (i >= NCH * 64 * 64) return;
    int c  = i & 63;
    int o  = (i >> 6) & 63;
    int ch = i >> 12;
    int k  = ch / 3;
    int cg = (ch % 3) * 64 + c;
    float v = __ldg(dw + o * (CIN3 * 9) + cg * 9 + k);
    __nv_bfloat16 hi = __float2bfloat16(v);
    __nv_bfloat16 lo = __float2bfloat16(v - __bfloat162float(hi));
    int elem = o * 64 + (((c >> 3) ^ (o & 7)) << 3) + (c & 7);
    wh[ch * 4096 + elem] = hi;
    wl[ch * 4096 + elem] = lo;
}

// ---------------------------------------------------------------------------
// Kernel 4: deformable conv, mma.sync bf16 hi/lo, double-buffered, with
// build quarters interleaved into the 4 GEMM k-steps (LSU/tensor overlap).
// Per buffer (48KB): A_hi@0 16K | A_lo@16K 16K | B_hi@32K 8K | B_lo@40K 8K
// ---------------------------------------------------------------------------
#define SM_BUF   49152
#define SM_AHOF  0
#define SM_ALOF  16384
#define SM_BHOF  32768
#define SM_BLOF  40960
#define SM_TOTAL (2 * SM_BUF)

__global__ __launch_bounds__(256, 2) void deform_kernel(
        const float* __restrict__ ref, const float* __restrict__ dist,
        const float* __restrict__ diffp,
        const float4* __restrict__ mw, const int4* __restrict__ mi,
        const __nv_bfloat16* __restrict__ wh, const __nv_bfloat16* __restrict__ wl,
        const float* __restrict__ db, float* __restrict__ out) {
    extern __shared__ char smem[];
    uint32_t sb = smem_to_u32(smem);

    int tid  = threadIdx.x;
    int lane = tid & 31;
    int warp = tid >> 5;
    int b    = blockIdx.x / 72;
    int pix0 = (blockIdx.x % 72) * 128;

    // A-build assignment: pixel p, channel half
    int p     = tid & 127;
    int chalf = tid >> 7;                 // 0/1 -> channels 0-31 / 32-63
    uint32_t a_sts = (uint32_t)p * 128;   // row base (bytes)

    // warp GEMM tile
    int m0 = (warp & 3) * 32;
    int n0 = (warp >> 2) * 32;

    const float* srcs[3];
    srcs[0] = ref   + b * IMG;
    srcs[1] = dist  + b * IMG;
    srcs[2] = diffp + b * IMG;

    float acc[2][4][4];
#pragma unroll
    for (int i = 0; i < 2; i++)
#pragma unroll
        for (int j = 0; j < 4; j++)
#pragma unroll
            for (int q = 0; q < 4; q++) acc[i][j][q] = 0.f;

    // ldmatrix lane addressing
    uint32_t a_m  = lane & 15;
    uint32_t a_kc = lane >> 4;
    uint32_t b_n  = ((lane >> 4) << 3) + (lane & 7);
    uint32_t b_kc = (lane >> 3) & 1;

    // B cp.async assignment
    int bcp0 = tid, bcp1 = tid + 256;

    // ---------- build one quarter (8 channels) of chunk ch ----------
    auto build_q = [&](int ch, int q, const float4& wgt, const int4& idx,
                       const float* src) {
        char* bufc = smem + (ch & 1) * SM_BUF;
        float v[8];
#pragma unroll
        for (int j = 0; j < 8; j++) {
            const float* pl = src + (size_t)(q * 8 + j) * HW;
            v[j] = wgt.x * __ldg(pl + idx.x) + wgt.y * __ldg(pl + idx.y)
                 + wgt.z * __ldg(pl + idx.z) + wgt.w * __ldg(pl + idx.w);
        }
        uint32_t hp[4], lp[4];
#pragma unroll
        for (int jj = 0; jj < 4; jj++) {
            __nv_bfloat162 hb = __float22bfloat162_rn(
                make_float2(v[2 * jj], v[2 * jj + 1]));
            hp[jj] = *(uint32_t*)&hb;
            float r0 = v[2 * jj]     - __bfloat162float(hb.x);
            float r1 = v[2 * jj + 1] - __bfloat162float(hb.y);
            __nv_bfloat162 lb = __float22bfloat162_rn(make_float2(r0, r1));
            lp[jj] = *(uint32_t*)&lb;
        }
        int kc = chalf * 4 + q;
        uint32_t off = a_sts + (uint32_t)((kc ^ (p & 7)) << 4);
        *(uint4*)(bufc + SM_AHOF + off) = make_uint4(hp[0], hp[1], hp[2], hp[3]);
        *(uint4*)(bufc + SM_ALOF + off) = make_uint4(lp[0], lp[1], lp[2], lp[3]);
    };

    auto stage_B = [&](int ch) {
        uint32_t bufb = sb + (ch & 1) * SM_BUF;
        const char* gh = (const char*)(wh + ch * 4096);
        const char* gl = (const char*)(wl + ch * 4096);
        cp_async16(bufb + SM_BHOF + bcp0 * 16, gh + bcp0 * 16);
        cp_async16(bufb + SM_BHOF + bcp1 * 16, gh + bcp1 * 16);
        cp_async16(bufb + SM_BLOF + bcp0 * 16, gl + bcp0 * 16);
        cp_async16(bufb + SM_BLOF + bcp1 * 16, gl + bcp1 * 16);
        CP_COMMIT();
    };

    // ---------- prologue: chunk 0 ----------
    stage_B(0);
    {
        float4 wgt = __ldg(mw + (b * 9 + 0) * HW + pix0 + p);
        int4   idx = __ldg(mi + (b * 9 + 0) * HW + pix0 + p);
        const float* src = srcs[0] + (size_t)(chalf * 32) * HW;
#pragma unroll
        for (int q = 0; q < 4; q++) build_q(0, q, wgt, idx, src);
    }
    CP_WAIT0();
    __syncthreads();

    for (int ch = 0; ch < NCH; ch++) {
        int nxt = ch + 1;
        bool has_nxt = (nxt < NCH);
        if (has_nxt) stage_B(nxt);

        // meta for next chunk
        float4 nwgt = make_float4(0, 0, 0, 0);
        int4   nidx = make_int4(0, 0, 0, 0);
        const float* nsrc = srcs[0];
        if (has_nxt) {
            int k = nxt / 3, cbl = nxt - 3 * k;
            nwgt = __ldg(mw + (b * 9 + k) * HW + pix0 + p);
            nidx = __ldg(mi + (b * 9 + k) * HW + pix0 + p);
            nsrc = srcs[cbl] + (size_t)(chalf * 32) * HW;
        }

        uint32_t bufb = sb + (ch & 1) * SM_BUF;
#pragma unroll
        for (int ks = 0; ks < 4; ks++) {
            uint32_t ah[2][4], al[2][4], bh[2][4], bl[2][4];
#pragma unroll
            for (int mi_ = 0; mi_ < 2; mi_++) {
                uint32_t row = m0 + mi_ * 16 + a_m;
                uint32_t aoff = row * 128 + ((((ks << 1) + a_kc) ^ (row & 7)) << 4);
                ldsm_x4(ah[mi_], bufb + SM_AHOF + aoff);
                ldsm_x4(al[mi_], bufb + SM_ALOF + aoff);
            }
#pragma unroll
            for (int g = 0; g < 2; g++) {
                uint32_t n  = n0 + g * 16 + b_n;
                uint32_t kc = (ks << 1) + b_kc;
                uint32_t boff = n * 128 + ((kc ^ (n & 7)) << 4);
                ldsm_x4(bh[g], bufb + SM_BHOF + boff);
                ldsm_x4(bl[g], bufb + SM_BLOF + boff);
            }
#pragma unroll
            for (int mi_ = 0; mi_ < 2; mi_++)
#pragma unroll
                for (int g = 0; g < 2; g++)
#pragma unroll
                    for (int s = 0; s < 2; s++) {
                        int ni = g * 2 + s;
                        mma_bf16(acc[mi_][ni], ah[mi_], bh[g][2 * s], bh[g][2 * s + 1]);
                        mma_bf16(acc[mi_][ni], ah[mi_], bl[g][2 * s], bl[g][2 * s + 1]);
                        mma_bf16(acc[mi_][ni], al[mi_], bh[g][2 * s], bh[g][2 * s + 1]);
                    }
            // interleaved build of next chunk's quarter ks
            if (has_nxt) build_q(nxt, ks, nwgt, nidx, nsrc);
        }

        CP_WAIT0();
        __syncthreads();
    }

    // ---- epilogue: bias + relu ----
    int r  = lane >> 2;
    int cp = (lane & 3) * 2;
#pragma unroll
    for (int mi_ = 0; mi_ < 2; mi_++) {
        int pixb = pix0 + m0 + mi_ * 16 + r;
#pragma unroll
        for (int ni = 0; ni < 4; ni++) {
            int o = n0 + ni * 8 + cp;
            float b0v = __ldg(db + o);
            float b1v = __ldg(db + o + 1);
            float* o0 = out + (size_t)(b * Oo + o) * HW;
            float* o1 = out + (size_t)(b * Oo + o + 1) * HW;
            float v;
            v = acc[mi_][ni][0] + b0v; o0[pixb]     = v > 0.f ? v : 0.f;
            v = acc[mi_][ni][1] + b1v; o1[pixb]     = v > 0.f ? v : 0.f;
            v = acc[mi_][ni][2] + b0v; o0[pixb + 8] = v > 0.f ? v : 0.f;
            v = acc[mi_][ni][3] + b1v; o1[pixb + 8] = v > 0.f ? v : 0.f;
        }
    }
}

// ---------------------------------------------------------------------------
extern "C" void kernel_launch(void* const* d_in, const int* in_sizes, int n_in,
                              void* d_out, int out_size) {
    const float* ref  = (const float*)d_in[0];
    const float* dist = (const float*)d_in[1];
    const float* ow   = (const float*)d_in[2];
    const float* ob   = (const float*)d_in[3];
    const float* dw   = (const float*)d_in[4];
    const float* db   = (const float*)d_in[5];
    float* out = (float*)d_out;
    float* out_feat = out;
    float* out_diff = out + Bb * IMG;

    float4* mw;     cudaGetSymbolAddress((void**)&mw, g_mw);
    int4*   mi;     cudaGetSymbolAddress((void**)&mi, g_mi);
    __nv_bfloat16* wh; cudaGetSymbolAddress((void**)&wh, g_wh);
    __nv_bfloat16* wl; cudaGetSymbolAddress((void**)&wl, g_wl);

    cudaFuncSetAttribute(deform_kernel,
                         cudaFuncAttributeMaxDynamicSharedMemorySize, SM_TOTAL);

    diff_kernel<<<(Bb * IMG + 255) / 256, 256>>>(ref, dist, out_diff);
    offset_meta_kernel<<<NPIX / 128, 128>>>(ref, ow, ob, mw, mi);
    wprep_kernel<<<(NCH * 64 * 64 + 255) / 256, 256>>>(dw, wh, wl);
    deform_kernel<<<NPIX / 128, 256, SM_TOTAL>>>(ref, dist, out_diff,
                                                 mw, mi, wh, wl, db, out_feat);
}

// round 7
// speedup vs baseline: 2.6582x; 1.0300x over previous
#include <cuda_runtime.h>
#include <cuda_fp16.h>
#include <math.h>
#include <stdint.h>

// Problem constants
#define Bb   4
#define Cc   64
#define Hh   96
#define Ww   96
#define HW   (Hh*Ww)            // 9216
#define Oo   64
#define CIN3 (3*Cc)             // 192
#define IMG  (Cc*HW)            // 589824
#define NPIX (Bb*HW)            // 36864
#define NCH  27                 // K chunks of 64: K = k*192 + c (k-major)

// Scratch
__device__ float4 g_mw[Bb * 9 * HW];
__device__ int4   g_mi[Bb * 9 * HW];
__device__ __half g_wh[NCH * 64 * 64];   // B tiles hi fp16 (pre-swizzled)

// ---------------- helpers ----------------
__device__ __forceinline__ uint32_t smem_to_u32(const void* p) {
    uint32_t a;
    asm("{ .reg .u64 t; cvta.to.shared.u64 t, %1; cvt.u32.u64 %0, t; }"
        : "=r"(a) : "l"(p));
    return a;
}
__device__ __forceinline__ void ldsm_x4(uint32_t* r, uint32_t addr) {
    asm volatile("ldmatrix.sync.aligned.m8n8.x4.shared.b16 {%0,%1,%2,%3}, [%4];"
        : "=r"(r[0]), "=r"(r[1]), "=r"(r[2]), "=r"(r[3]) : "r"(addr));
}
__device__ __forceinline__ void mma_f16(float* d, const uint32_t* a,
                                        uint32_t b0, uint32_t b1) {
    asm volatile("mma.sync.aligned.m16n8k16.row.col.f32.f16.f16.f32 "
        "{%0,%1,%2,%3}, {%4,%5,%6,%7}, {%8,%9}, {%0,%1,%2,%3};"
        : "+f"(d[0]), "+f"(d[1]), "+f"(d[2]), "+f"(d[3])
        : "r"(a[0]), "r"(a[1]), "r"(a[2]), "r"(a[3]), "r"(b0), "r"(b1));
}
__device__ __forceinline__ void cp_async16(uint32_t smem_addr, const void* gptr) {
    asm volatile("cp.async.cg.shared.global [%0], [%1], 16;"
        :: "r"(smem_addr), "l"(gptr));
}
#define CP_COMMIT() asm volatile("cp.async.commit_group;" ::: "memory")
#define CP_WAIT0()  asm volatile("cp.async.wait_group 0;" ::: "memory")

// ---------------------------------------------------------------------------
// Kernel 1 (merged prolog): block-range dispatch
//   blocks [0,288):    offset conv3x3 + fused bilinear meta (128 thr = 128 px)
//   blocks [288,576):  diff = (ref-dist)^2  (float4 grid-stride)
//   blocks [576,672):  weight prep -> fp16 B tiles, XOR-swizzled [n][k]
// ---------------------------------------------------------------------------
__global__ __launch_bounds__(128) void prolog_kernel(
        const float* __restrict__ ref, const float* __restrict__ dist,
        const float* __restrict__ ow, const float* __restrict__ ob,
        const float* __restrict__ dw,
        float* __restrict__ out_diff,
        float4* __restrict__ mw, int4* __restrict__ mi,
        __half* __restrict__ wh) {
    int tid = threadIdx.x;
    int bid = blockIdx.x;

    if (bid >= 576) {
        // ---- wprep: 96 blocks x 128 thr, 9 grid-stride iters ----
        for (int i = (bid - 576) * 128 + tid; i < NCH * 64 * 64; i += 96 * 128) {
            int c  = i & 63;
            int o  = (i >> 6) & 63;
            int ch = i >> 12;
            int k  = ch / 3;
            int cg = (ch % 3) * 64 + c;
            float v = __ldg(dw + o * (CIN3 * 9) + cg * 9 + k);
            int elem = o * 64 + (((c >> 3) ^ (o & 7)) << 3) + (c & 7);
            wh[ch * 4096 + elem] = __float2half_rn(v);
        }
        return;
    }
    if (bid >= 288) {
        // ---- diff: 288 blocks, float4, 16 iters ----
        const float4* r4 = (const float4*)ref;
        const float4* d4 = (const float4*)dist;
        float4* o4 = (float4*)out_diff;
        for (int i = (bid - 288) * 128 + tid; i < (Bb * IMG) / 4; i += 288 * 128) {
            float4 a = __ldg(r4 + i), b = __ldg(d4 + i);
            float4 v;
            v.x = (a.x - b.x) * (a.x - b.x);
            v.y = (a.y - b.y) * (a.y - b.y);
            v.z = (a.z - b.z) * (a.z - b.z);
            v.w = (a.w - b.w) * (a.w - b.w);
            o4[i] = v;
        }
        return;
    }

    // ---- offset conv + meta ----
    __shared__ __align__(16) float s_w[576 * 20];
    for (int i = tid; i < 18 * 576; i += 128) {
        int o = i / 576, ck = i % 576;
        s_w[ck * 20 + o] = ow[i];
    }
    __syncthreads();

    int p = bid * 128 + tid;
    int b = p / HW;
    int pix = p % HW;
    int y = pix / Ww, x = pix % Ww;

    int  idx9[9]; bool ok9[9];
#pragma unroll
    for (int ky = 0; ky < 3; ky++)
#pragma unroll
        for (int kx = 0; kx < 3; kx++) {
            int yy = y + ky - 1, xx = x + kx - 1;
            bool ok = (yy >= 0) && (yy < Hh) && (xx >= 0) && (xx < Ww);
            ok9[ky * 3 + kx] = ok;
            idx9[ky * 3 + kx] = (ok ? yy : 0) * Ww + (ok ? xx : 0);
        }

    float acc[18];
#pragma unroll
    for (int o = 0; o < 18; o++) acc[o] = 0.f;

    const float* xb = ref + b * IMG;
    for (int c = 0; c < Cc; c++) {
        const float* xc = xb + c * HW;
#pragma unroll
        for (int k = 0; k < 9; k++) {
            float v = ok9[k] ? __ldg(xc + idx9[k]) : 0.f;
            int base = (c * 9 + k) * 20;
            float4 w0 = *(const float4*)&s_w[base];
            float4 w1 = *(const float4*)&s_w[base + 4];
            float4 w2 = *(const float4*)&s_w[base + 8];
            float4 w3 = *(const float4*)&s_w[base + 12];
            float  wa = s_w[base + 16];
            float  wb = s_w[base + 17];
            acc[0]  += v * w0.x;  acc[1]  += v * w0.y;  acc[2]  += v * w0.z;  acc[3]  += v * w0.w;
            acc[4]  += v * w1.x;  acc[5]  += v * w1.y;  acc[6]  += v * w1.z;  acc[7]  += v * w1.w;
            acc[8]  += v * w2.x;  acc[9]  += v * w2.y;  acc[10] += v * w2.z;  acc[11] += v * w2.w;
            acc[12] += v * w3.x;  acc[13] += v * w3.y;  acc[14] += v * w3.z;  acc[15] += v * w3.w;
            acc[16] += v * wa;    acc[17] += v * wb;
        }
    }

#pragma unroll
    for (int k = 0; k < 9; k++) {
        float offy = acc[2 * k]     + __ldg(ob + 2 * k);
        float offx = acc[2 * k + 1] + __ldg(ob + 2 * k + 1);
        float py = (float)(y - 1 + k / 3) + offy;
        float px = (float)(x - 1 + k % 3) + offx;
        float fy = floorf(py), fx = floorf(px);
        int y0 = (int)fy, x0 = (int)fx;
        float dy = py - fy, dx = px - fx;
        float wv[4]; int iv[4];
#pragma unroll
        for (int t = 0; t < 4; t++) {
            int yt = y0 + (t >> 1);
            int xt = x0 + (t & 1);
            float wt = ((t >> 1) ? dy : (1.f - dy)) * ((t & 1) ? dx : (1.f - dx));
            bool valid = (yt >= 0) && (yt < Hh) && (xt >= 0) && (xt < Ww);
            int yc = yt < 0 ? 0 : (yt > Hh - 1 ? Hh - 1 : yt);
            int xc = xt < 0 ? 0 : (xt > Ww - 1 ? Ww - 1 : xt);
            wv[t] = valid ? wt : 0.f;
            iv[t] = yc * Ww + xc;
        }
        int mo = (b * 9 + k) * HW + pix;
        mw[mo] = make_float4(wv[0], wv[1], wv[2], wv[3]);
        mi[mo] = make_int4(iv[0], iv[1], iv[2], iv[3]);
    }
}

// ---------------------------------------------------------------------------
// Kernel 2: deformable conv, mma.sync fp16: (A_hi + A_lo) x B_hi.
// Double-buffered; build quarters interleaved into the 4 GEMM k-steps.
// Per buffer (40KB): A_hi@0 16K | A_lo@16K 16K | B_hi@32K 8K
// ---------------------------------------------------------------------------
#define SM_BUF   40960
#define SM_AHOF  0
#define SM_ALOF  16384
#define SM_BHOF  32768
#define SM_TOTAL (2 * SM_BUF)

__global__ __launch_bounds__(256, 2) void deform_kernel(
        const float* __restrict__ ref, const float* __restrict__ dist,
        const float* __restrict__ diffp,
        const float4* __restrict__ mw, const int4* __restrict__ mi,
        const __half* __restrict__ wh,
        const float* __restrict__ db, float* __restrict__ out) {
    extern __shared__ char smem[];
    uint32_t sb = smem_to_u32(smem);

    int tid  = threadIdx.x;
    int lane = tid & 31;
    int warp = tid >> 5;
    int b    = blockIdx.x / 72;
    int pix0 = (blockIdx.x % 72) * 128;

    int p     = tid & 127;
    int chalf = tid >> 7;
    uint32_t a_sts = (uint32_t)p * 128;

    int m0 = (warp & 3) * 32;
    int n0 = (warp >> 2) * 32;

    const float* srcs[3];
    srcs[0] = ref   + b * IMG;
    srcs[1] = dist  + b * IMG;
    srcs[2] = diffp + b * IMG;

    float acc[2][4][4];
#pragma unroll
    for (int i = 0; i < 2; i++)
#pragma unroll
        for (int j = 0; j < 4; j++)
#pragma unroll
            for (int q = 0; q < 4; q++) acc[i][j][q] = 0.f;

    uint32_t a_m  = lane & 15;
    uint32_t a_kc = lane >> 4;
    uint32_t b_n  = ((lane >> 4) << 3) + (lane & 7);
    uint32_t b_kc = (lane >> 3) & 1;

    int bcp0 = tid, bcp1 = tid + 256;

    // build one quarter (8 channels) of chunk ch
    auto build_q = [&](int ch, int q, const float4& wgt, const int4& idx,
                       const float* src) {
        char* bufc = smem + (ch & 1) * SM_BUF;
        float v[8];
#pragma unroll
        for (int j = 0; j < 8; j++) {
            const float* pl = src + (size_t)(q * 8 + j) * HW;
            v[j] = wgt.x * __ldg(pl + idx.x) + wgt.y * __ldg(pl + idx.y)
                 + wgt.z * __ldg(pl + idx.z) + wgt.w * __ldg(pl + idx.w);
        }
        uint32_t hp[4], lp[4];
#pragma unroll
        for (int jj = 0; jj < 4; jj++) {
            __half h0 = __float2half_rn(v[2 * jj]);
            __half h1 = __float2half_rn(v[2 * jj + 1]);
            __half2 hb = __halves2half2(h0, h1);
            hp[jj] = *(uint32_t*)&hb;
            float r0 = v[2 * jj]     - __half2float(h0);
            float r1 = v[2 * jj + 1] - __half2float(h1);
            __half2 lb = __halves2half2(__float2half_rn(r0), __float2half_rn(r1));
            lp[jj] = *(uint32_t*)&lb;
        }
        int kc = chalf * 4 + q;
        uint32_t off = a_sts + (uint32_t)((kc ^ (p & 7)) << 4);
        *(uint4*)(bufc + SM_AHOF + off) = make_uint4(hp[0], hp[1], hp[2], hp[3]);
        *(uint4*)(bufc + SM_ALOF + off) = make_uint4(lp[0], lp[1], lp[2], lp[3]);
    };

    auto stage_B = [&](int ch) {
        uint32_t bufb = sb + (ch & 1) * SM_BUF;
        const char* gh = (const char*)(wh + ch * 4096);
        cp_async16(bufb + SM_BHOF + bcp0 * 16, gh + bcp0 * 16);
        cp_async16(bufb + SM_BHOF + bcp1 * 16, gh + bcp1 * 16);
        CP_COMMIT();
    };

    // prologue: chunk 0
    stage_B(0);
    {
        float4 wgt = __ldg(mw + (b * 9 + 0) * HW + pix0 + p);
        int4   idx = __ldg(mi + (b * 9 + 0) * HW + pix0 + p);
        const float* src = srcs[0] + (size_t)(chalf * 32) * HW;
#pragma unroll
        for (int q = 0; q < 4; q++) build_q(0, q, wgt, idx, src);
    }
    CP_WAIT0();
    __syncthreads();

    for (int ch = 0; ch < NCH; ch++) {
        int nxt = ch + 1;
        bool has_nxt = (nxt < NCH);
        if (has_nxt) stage_B(nxt);

        float4 nwgt = make_float4(0, 0, 0, 0);
        int4   nidx = make_int4(0, 0, 0, 0);
        const float* nsrc = srcs[0];
        if (has_nxt) {
            int k = nxt / 3, cbl = nxt - 3 * k;
            nwgt = __ldg(mw + (b * 9 + k) * HW + pix0 + p);
            nidx = __ldg(mi + (b * 9 + k) * HW + pix0 + p);
            nsrc = srcs[cbl] + (size_t)(chalf * 32) * HW;
        }

        uint32_t bufb = sb + (ch & 1) * SM_BUF;
#pragma unroll
        for (int ks = 0; ks < 4; ks++) {
            uint32_t ah[2][4], al[2][4], bh[2][4];
#pragma unroll
            for (int mi_ = 0; mi_ < 2; mi_++) {
                uint32_t row = m0 + mi_ * 16 + a_m;
                uint32_t aoff = row * 128 + ((((ks << 1) + a_kc) ^ (row & 7)) << 4);
                ldsm_x4(ah[mi_], bufb + SM_AHOF + aoff);
                ldsm_x4(al[mi_], bufb + SM_ALOF + aoff);
            }
#pragma unroll
            for (int g = 0; g < 2; g++) {
                uint32_t n  = n0 + g * 16 + b_n;
                uint32_t kc = (ks << 1) + b_kc;
                uint32_t boff = n * 128 + ((kc ^ (n & 7)) << 4);
                ldsm_x4(bh[g], bufb + SM_BHOF + boff);
            }
#pragma unroll
            for (int mi_ = 0; mi_ < 2; mi_++)
#pragma unroll
                for (int g = 0; g < 2; g++)
#pragma unroll
                    for (int s = 0; s < 2; s++) {
                        int ni = g * 2 + s;
                        mma_f16(acc[mi_][ni], ah[mi_], bh[g][2 * s], bh[g][2 * s + 1]);
                        mma_f16(acc[mi_][ni], al[mi_], bh[g][2 * s], bh[g][2 * s + 1]);
                    }
            if (has_nxt) build_q(nxt, ks, nwgt, nidx, nsrc);
        }

        CP_WAIT0();
        __syncthreads();
    }

    // epilogue: bias + relu
    int r  = lane >> 2;
    int cp = (lane & 3) * 2;
#pragma unroll
    for (int mi_ = 0; mi_ < 2; mi_++) {
        int pixb = pix0 + m0 + mi_ * 16 + r;
#pragma unroll
        for (int ni = 0; ni < 4; ni++) {
            int o = n0 + ni * 8 + cp;
            float b0v = __ldg(db + o);
            float b1v = __ldg(db + o + 1);
            float* o0 = out + (size_t)(b * Oo + o) * HW;
            float* o1 = out + (size_t)(b * Oo + o + 1) * HW;
            float v;
            v = acc[mi_][ni][0] + b0v; o0[pixb]     = v > 0.f ? v : 0.f;
            v = acc[mi_][ni][1] + b1v; o1[pixb]     = v > 0.f ? v : 0.f;
            v = acc[mi_][ni][2] + b0v; o0[pixb + 8] = v > 0.f ? v : 0.f;
            v = acc[mi_][ni][3] + b1v; o1[pixb + 8] = v > 0.f ? v : 0.f;
        }
    }
}

// ---------------------------------------------------------------------------
extern "C" void kernel_launch(void* const* d_in, const int* in_sizes, int n_in,
                              void* d_out, int out_size) {
    const float* ref  = (const float*)d_in[0];
    const float* dist = (const float*)d_in[1];
    const float* ow   = (const float*)d_in[2];
    const float* ob   = (const float*)d_in[3];
    const float* dw   = (const float*)d_in[4];
    const float* db   = (const float*)d_in[5];
    float* out = (float*)d_out;
    float* out_feat = out;
    float* out_diff = out + Bb * IMG;

    float4* mw;  cudaGetSymbolAddress((void**)&mw, g_mw);
    int4*   mi;  cudaGetSymbolAddress((void**)&mi, g_mi);
    __half* wh;  cudaGetSymbolAddress((void**)&wh, g_wh);

    cudaFuncSetAttribute(deform_kernel,
                         cudaFuncAttributeMaxDynamicSharedMemorySize, SM_TOTAL);

    prolog_kernel<<<672, 128>>>(ref, dist, ow, ob, dw, out_diff, mw, mi, wh);
    deform_kernel<<<NPIX / 128, 256, SM_TOTAL>>>(ref, dist, out_diff,
                                                 mw, mi, wh, db, out_feat);
}